// round 2
// baseline (speedup 1.0000x reference)
#include <cuda_runtime.h>

#define IMG   64
#define CH    16
#define B     8
#define N_PIX 4096   // 64*64

// ---------------- scratch (no allocations allowed) ----------------
__device__ float g_buf0[B * CH * N_PIX];
__device__ float g_buf1[B * CH * N_PIX];
__device__ float g_xc  [B * CH * N_PIX];
__device__ float g_invs[B * N_PIX];

// ---------------- conv0: 1 -> 16 channels, 5x5 'same' ----------------
__global__ void conv0_kernel(const float* __restrict__ x,
                             const float* __restrict__ w,
                             const float* __restrict__ bias) {
    int id  = blockIdx.x * blockDim.x + threadIdx.x;  // b*16*4096 total
    int pix = id & 4095;
    int oc  = (id >> 12) & 15;
    int b   = id >> 16;
    int py = pix >> 6, px = pix & 63;
    const float* xin = x + b * N_PIX;
    float acc = __ldg(bias + oc);
    #pragma unroll
    for (int ky = 0; ky < 5; ky++) {
        int gy = py + ky - 2;
        if (gy < 0 || gy >= IMG) continue;
        #pragma unroll
        for (int kx = 0; kx < 5; kx++) {
            int gx = px + kx - 2;
            if (gx < 0 || gx >= IMG) continue;
            acc = fmaf(xin[gy * IMG + gx], __ldg(w + oc * 25 + ky * 5 + kx), acc);
        }
    }
    g_buf0[id] = acc;
}

// ---------------- conv16: 16 -> 16 channels, 5x5 'same' ----------------
// Block: 128 threads = 32x4 output tile. SMEM: input halo tile + padded weights.
// dir=0: g_buf0 -> g_buf1 ; dir=1: g_buf1 -> g_buf0
__global__ void conv16_kernel(const float* __restrict__ w,
                              const float* __restrict__ bias, int dir) {
    __shared__ float sin_t[CH * 8 * 36];                 // 18432 B
    __shared__ __align__(16) float sw[CH * CH * 28];     // 28672 B (25 padded to 28)
    const float* in  = dir ? g_buf1 : g_buf0;
    float*       out = dir ? g_buf0 : g_buf1;

    int tid  = threadIdx.x;   // 0..127
    int b    = blockIdx.y;
    int tile = blockIdx.x;    // 0..31
    int tx0  = (tile & 1) * 32;
    int ty0  = (tile >> 1) * 4;

    // weights -> SMEM, padded stride 28 so each (oc,ic) row is 16B-aligned
    for (int idx = tid; idx < CH * CH * 25; idx += 128) {
        int oc = idx / 400;
        int rem = idx - oc * 400;
        int ic = rem / 25;
        int k  = rem - ic * 25;
        sw[(oc * 16 + ic) * 28 + k] = w[idx];
    }
    // input halo tile -> SMEM (8 rows x 36 cols per channel)
    const float* inb = in + b * CH * N_PIX;
    for (int idx = tid; idx < CH * 8 * 36; idx += 128) {
        int c   = idx / 288;
        int rem = idx - c * 288;
        int r   = rem / 36;
        int cc  = rem - r * 36;
        int gy = ty0 + r - 2;
        int gx = tx0 + cc - 2;
        float v = 0.f;
        if (gy >= 0 && gy < IMG && gx >= 0 && gx < IMG)
            v = inb[c * N_PIX + gy * IMG + gx];
        sin_t[idx] = v;
    }
    __syncthreads();

    int tx = tid & 31, ty = tid >> 5;
    float acc[16];
    #pragma unroll
    for (int oc = 0; oc < 16; oc++) acc[oc] = __ldg(bias + oc);

    #pragma unroll 1
    for (int ic = 0; ic < 16; ic++) {
        float t[25];
        #pragma unroll
        for (int ky = 0; ky < 5; ky++)
            #pragma unroll
            for (int kx = 0; kx < 5; kx++)
                t[ky * 5 + kx] = sin_t[ic * 288 + (ty + ky) * 36 + tx + kx];
        #pragma unroll
        for (int oc = 0; oc < 16; oc++) {
            const float*  wp  = &sw[(oc * 16 + ic) * 28];
            const float4* wp4 = reinterpret_cast<const float4*>(wp);
            #pragma unroll
            for (int q = 0; q < 6; q++) {
                float4 wv = wp4[q];
                acc[oc] = fmaf(t[q * 4 + 0], wv.x, acc[oc]);
                acc[oc] = fmaf(t[q * 4 + 1], wv.y, acc[oc]);
                acc[oc] = fmaf(t[q * 4 + 2], wv.z, acc[oc]);
                acc[oc] = fmaf(t[q * 4 + 3], wv.w, acc[oc]);
            }
            acc[oc] = fmaf(t[24], wp[24], acc[oc]);
        }
    }

    int py = ty0 + ty, px = tx0 + tx;
    float* outb = out + b * CH * N_PIX + py * IMG + px;
    #pragma unroll
    for (int oc = 0; oc < 16; oc++)
        outb[oc * N_PIX] = acc[oc];
}

// ---------------- stats: per-pixel mean / unbiased std over 16 channels ----------------
__global__ void stats_kernel() {
    int id  = blockIdx.x * 256 + threadIdx.x;   // b*4096 + pix, 32768 total
    int b   = id >> 12;
    int pix = id & 4095;
    const float* p = g_buf0 + b * CH * N_PIX + pix;  // conv2 output lives in g_buf0
    float v[16];
    float s = 0.f;
    #pragma unroll
    for (int c = 0; c < 16; c++) { v[c] = p[c * N_PIX]; s += v[c]; }
    float mean = s * (1.f / 16.f);
    float var = 0.f;
    #pragma unroll
    for (int c = 0; c < 16; c++) {
        float d = v[c] - mean;
        var = fmaf(d, d, var);
        g_xc[b * CH * N_PIX + c * N_PIX + pix] = d;
    }
    var *= (1.f / 15.f);        // ddof = 1
    g_invs[id] = 1.f / sqrtf(var);
}

// ---------------- coupling: out[b,i,j] = (xc_i . xc_j)/16 * s_i * s_j * mask ----------------
// Symmetric: only tj >= ti tiles computed; transpose mirrored via SMEM staging.
// f32x2 packed FMAs halve the FFMA instruction count.
__global__ void __launch_bounds__(256) coupling_kernel(const float* __restrict__ mask,
                                                       float* __restrict__ out) {
    __shared__ __align__(16) float sxi[16 * 64];
    __shared__ __align__(16) float sxj[16 * 64];
    __shared__ float sii[64];
    __shared__ float sij[64];
    __shared__ float stg[64 * 65];

    int b = blockIdx.x;             // batch fastest -> mask tiles reused in L2 across batches
    int p = blockIdx.y;             // 0..2079 triangular pair index (T=64)

    // decode (ti, tj), tj >= ti
    int ti = (int)((129.0f - sqrtf(129.0f * 129.0f - 8.0f * (float)p)) * 0.5f);
    while (((ti + 1) * 64 - ((ti + 1) * ti) / 2) <= p) ti++;
    while ((ti * 64 - (ti * (ti - 1)) / 2) > p) ti--;
    int tj = ti + (p - (ti * 64 - (ti * (ti - 1)) / 2));
    bool diag = (ti == tj);

    int tid = threadIdx.x;
    const float* xcb = g_xc + b * CH * N_PIX;
    for (int idx = tid; idx < 1024; idx += 256) {
        int c = idx >> 6, col = idx & 63;
        sxi[idx] = xcb[c * N_PIX + ti * 64 + col];
        sxj[idx] = xcb[c * N_PIX + tj * 64 + col];
    }
    if (tid < 64)       sii[tid]      = g_invs[b * N_PIX + ti * 64 + tid];
    else if (tid < 128) sij[tid - 64] = g_invs[b * N_PIX + tj * 64 + tid - 64];
    __syncthreads();

    int txj = tid & 15, tyi = tid >> 4;
    int jl = txj * 4, il = tyi * 4;

    unsigned long long a0[4], a1[4];
    #pragma unroll
    for (int ii = 0; ii < 4; ii++) { a0[ii] = 0ULL; a1[ii] = 0ULL; }

    #pragma unroll
    for (int c = 0; c < 16; c++) {
        unsigned long long pb0 = *reinterpret_cast<const unsigned long long*>(&sxj[c * 64 + jl]);
        unsigned long long pb1 = *reinterpret_cast<const unsigned long long*>(&sxj[c * 64 + jl + 2]);
        #pragma unroll
        for (int ii = 0; ii < 4; ii++) {
            float av = sxi[c * 64 + il + ii];
            unsigned long long pa;
            asm("mov.b64 %0, {%1, %1};" : "=l"(pa) : "f"(av));
            asm("fma.rn.f32x2 %0, %1, %2, %0;" : "+l"(a0[ii]) : "l"(pa), "l"(pb0));
            asm("fma.rn.f32x2 %0, %1, %2, %0;" : "+l"(a1[ii]) : "l"(pa), "l"(pb1));
        }
    }

    float sj0 = sij[jl], sj1 = sij[jl + 1], sj2 = sij[jl + 2], sj3 = sij[jl + 3];
    size_t obase = (size_t)b * N_PIX * N_PIX;

    #pragma unroll
    for (int ii = 0; ii < 4; ii++) {
        float v0, v1, v2, v3;
        asm("mov.b64 {%0, %1}, %2;" : "=f"(v0), "=f"(v1) : "l"(a0[ii]));
        asm("mov.b64 {%0, %1}, %2;" : "=f"(v2), "=f"(v3) : "l"(a1[ii]));
        float si = sii[il + ii] * 0.0625f;     // fold /16
        v0 *= si * sj0; v1 *= si * sj1; v2 *= si * sj2; v3 *= si * sj3;

        if (!diag) {   // transposed staging for mirror write (mask not applied yet)
            stg[(jl + 0) * 65 + il + ii] = v0;
            stg[(jl + 1) * 65 + il + ii] = v1;
            stg[(jl + 2) * 65 + il + ii] = v2;
            stg[(jl + 3) * 65 + il + ii] = v3;
        }

        int ig = ti * 64 + il + ii;
        int jg = tj * 64 + jl;
        float4 m = *reinterpret_cast<const float4*>(mask + (size_t)ig * N_PIX + jg);
        float4 o = make_float4(v0 * m.x, v1 * m.y, v2 * m.z, v3 * m.w);
        *reinterpret_cast<float4*>(out + obase + (size_t)ig * N_PIX + jg) = o;
    }

    if (!diag) {   // block-uniform branch -> syncthreads is safe
        __syncthreads();
        #pragma unroll
        for (int rr = 0; rr < 4; rr++) {
            int r  = il + rr;                // local j row
            int jg = tj * 64 + r;
            int c0 = jl;                     // local i col
            float s0 = stg[r * 65 + c0 + 0];
            float s1 = stg[r * 65 + c0 + 1];
            float s2 = stg[r * 65 + c0 + 2];
            float s3 = stg[r * 65 + c0 + 3];
            float4 m = *reinterpret_cast<const float4*>(mask + (size_t)jg * N_PIX + ti * 64 + c0);
            float4 o = make_float4(s0 * m.x, s1 * m.y, s2 * m.z, s3 * m.w);
            *reinterpret_cast<float4*>(out + obase + (size_t)jg * N_PIX + ti * 64 + c0) = o;
        }
    }
}

// ---------------- launch ----------------
extern "C" void kernel_launch(void* const* d_in, const int* in_sizes, int n_in,
                              void* d_out, int out_size) {
    const float* x    = (const float*)d_in[0];
    const float* w0   = (const float*)d_in[1];
    const float* b0   = (const float*)d_in[2];
    const float* w1   = (const float*)d_in[3];
    const float* b1   = (const float*)d_in[4];
    const float* w2   = (const float*)d_in[5];
    const float* b2   = (const float*)d_in[6];
    const float* mask = (const float*)d_in[7];
    float* out = (float*)d_out;

    conv0_kernel<<<(B * CH * N_PIX) / 256, 256>>>(x, w0, b0);          // x -> g_buf0
    conv16_kernel<<<dim3(32, B), 128>>>(w1, b1, /*dir=*/0);            // g_buf0 -> g_buf1
    conv16_kernel<<<dim3(32, B), 128>>>(w2, b2, /*dir=*/1);            // g_buf1 -> g_buf0
    stats_kernel<<<(B * N_PIX) / 256, 256>>>();                        // g_buf0 -> g_xc, g_invs
    coupling_kernel<<<dim3(B, 2080), 256>>>(mask, out);                // -> d_out
}

// round 3
// speedup vs baseline: 1.0503x; 1.0503x over previous
#include <cuda_runtime.h>

#define IMG   64
#define CH    16
#define B     8
#define N_PIX 4096   // 64*64

// ---------------- scratch (no allocations allowed) ----------------
__device__ float g_buf0[B * CH * N_PIX];
__device__ float g_buf1[B * CH * N_PIX];
__device__ float g_xc  [B * CH * N_PIX];
__device__ float g_invs[B * N_PIX];

// packed conv weights, pair = {w[2*ocp], w[2*ocp+1]} for (ic,ky,kx)
// a-array: first 4 kx of each (ocp,ic,ky) row (16B-aligned groups), b-array: 5th kx
__device__ unsigned long long g_w1pa[8 * 16 * 5 * 4];
__device__ unsigned long long g_w1pb[8 * 16 * 5];
__device__ unsigned long long g_w2pa[8 * 16 * 5 * 4];
__device__ unsigned long long g_w2pb[8 * 16 * 5];
__device__ unsigned long long g_b1p[8];
__device__ unsigned long long g_b2p[8];

#define FMA2(acc, a, b) asm("fma.rn.f32x2 %0, %1, %2, %0;" : "+l"(acc) : "l"(a), "l"(b))
#define DUP2(p, v)      asm("mov.b64 %0, {%1, %1};" : "=l"(p) : "f"(v))
#define PACK2(p, lo, hi) asm("mov.b64 %0, {%1, %2};" : "=l"(p) : "f"(lo), "f"(hi))
#define UNPK2(lo, hi, p) asm("mov.b64 {%0, %1}, %2;" : "=f"(lo), "=f"(hi) : "l"(p))

// ---------------- prep: pack weight/bias pairs ----------------
__global__ void prep_kernel(const float* __restrict__ w1, const float* __restrict__ b1,
                            const float* __restrict__ w2, const float* __restrict__ b2) {
    int idx = blockIdx.x * 256 + threadIdx.x;
    if (idx < 6400) {
        int which = idx >= 3200;                 // 0: w1, 1: w2
        int r = which ? idx - 3200 : idx;        // ((ocp*16+ic)*5+ky)*5+kx
        int kx = r % 5;
        int g  = r / 5;                          // (ocp*16+ic)*5+ky
        int ky = g % 5;
        int ocic = g / 5;
        int ic  = ocic & 15;
        int ocp = ocic >> 4;
        const float* w = which ? w2 : w1;
        float lo = w[(2 * ocp) * 400 + ic * 25 + ky * 5 + kx];
        float hi = w[(2 * ocp + 1) * 400 + ic * 25 + ky * 5 + kx];
        unsigned long long p;
        PACK2(p, lo, hi);
        if (kx < 4) { (which ? g_w2pa : g_w1pa)[g * 4 + kx] = p; }
        else        { (which ? g_w2pb : g_w1pb)[g]          = p; }
    } else if (idx < 6416) {
        int k = idx - 6400;
        int which = k >= 8;
        int p = k & 7;
        const float* bb = which ? b2 : b1;
        unsigned long long pr;
        PACK2(pr, bb[2 * p], bb[2 * p + 1]);
        (which ? g_b2p : g_b1p)[p] = pr;
    }
}

// ---------------- conv0: 1 -> 16 channels, 5x5 'same' ----------------
__global__ void conv0_kernel(const float* __restrict__ x,
                             const float* __restrict__ w,
                             const float* __restrict__ bias) {
    int id  = blockIdx.x * blockDim.x + threadIdx.x;  // b*16*4096 total
    int pix = id & 4095;
    int oc  = (id >> 12) & 15;
    int b   = id >> 16;
    int py = pix >> 6, px = pix & 63;
    const float* xin = x + b * N_PIX;
    float acc = __ldg(bias + oc);
    #pragma unroll
    for (int ky = 0; ky < 5; ky++) {
        int gy = py + ky - 2;
        if (gy < 0 || gy >= IMG) continue;
        #pragma unroll
        for (int kx = 0; kx < 5; kx++) {
            int gx = px + kx - 2;
            if (gx < 0 || gx >= IMG) continue;
            acc = fmaf(xin[gy * IMG + gx], __ldg(w + oc * 25 + ky * 5 + kx), acc);
        }
    }
    g_buf0[id] = acc;
}

// ---------------- conv16 (f32x2, oc-paired). FUSE=true: conv2 + stats fused ----------------
// Block: 128 threads = one 32x4 output tile, NOCP oc-pairs per thread.
template<int NOCP, bool FUSE>
__global__ void __launch_bounds__(128) conv16p_kernel() {
    __shared__ float sin_t[CH * 8 * 36];                   // 18432 B
    __shared__ __align__(16) unsigned long long swa[NOCP * 16 * 5 * 4];
    __shared__ unsigned long long swb[NOCP * 16 * 5];

    const float* in = FUSE ? g_buf1 : g_buf0;
    const unsigned long long* gwa = FUSE ? g_w2pa : g_w1pa;
    const unsigned long long* gwb = FUSE ? g_w2pb : g_w1pb;
    const unsigned long long* gbp = FUSE ? g_b2p  : g_b1p;

    int tid  = threadIdx.x;
    int tile = blockIdx.x;                       // 0..31
    int h    = FUSE ? 0 : blockIdx.y;            // oc-half for conv1
    int b    = FUSE ? blockIdx.y : blockIdx.z;
    int tx0  = (tile & 1) * 32;
    int ty0  = (tile >> 1) * 4;

    // packed weights -> SMEM
    int abase = h * NOCP * 16 * 5 * 4;
    int bbase = h * NOCP * 16 * 5;
    for (int i = tid; i < NOCP * 16 * 5 * 4; i += 128) swa[i] = gwa[abase + i];
    for (int i = tid; i < NOCP * 16 * 5;     i += 128) swb[i] = gwb[bbase + i];

    // input halo tile -> SMEM (8 rows x 36 cols per channel)
    const float* inb = in + b * CH * N_PIX;
    for (int idx = tid; idx < CH * 8 * 36; idx += 128) {
        int c   = idx / 288;
        int rem = idx - c * 288;
        int r   = rem / 36;
        int cc  = rem - r * 36;
        int gy = ty0 + r - 2;
        int gx = tx0 + cc - 2;
        float v = 0.f;
        if (gy >= 0 && gy < IMG && gx >= 0 && gx < IMG)
            v = inb[c * N_PIX + gy * IMG + gx];
        sin_t[idx] = v;
    }
    __syncthreads();

    int tx = tid & 31, ty = tid >> 5;
    unsigned long long acc[NOCP];
    #pragma unroll
    for (int p = 0; p < NOCP; p++) acc[p] = gbp[h * NOCP + p];

    #pragma unroll 1
    for (int ic = 0; ic < 16; ic++) {
        const float* srow = &sin_t[ic * 288 + ty * 36 + tx];
        #pragma unroll
        for (int ky = 0; ky < 5; ky++) {
            const float* rr = srow + ky * 36;
            unsigned long long pa0, pa1, pa2, pa3, pa4;
            DUP2(pa0, rr[0]); DUP2(pa1, rr[1]); DUP2(pa2, rr[2]);
            DUP2(pa3, rr[3]); DUP2(pa4, rr[4]);
            #pragma unroll
            for (int p = 0; p < NOCP; p++) {
                int g = (p * 16 + ic) * 5 + ky;
                const ulonglong2* wq = reinterpret_cast<const ulonglong2*>(&swa[g * 4]);
                ulonglong2 q0 = wq[0];
                ulonglong2 q1 = wq[1];
                unsigned long long w4 = swb[g];
                FMA2(acc[p], pa0, q0.x);
                FMA2(acc[p], pa1, q0.y);
                FMA2(acc[p], pa2, q1.x);
                FMA2(acc[p], pa3, q1.y);
                FMA2(acc[p], pa4, w4);
            }
        }
    }

    int py = ty0 + ty, px = tx0 + tx;
    int pix = py * IMG + px;

    if (!FUSE) {
        float* outb = g_buf1 + b * CH * N_PIX + (h * NOCP * 2) * N_PIX + pix;
        #pragma unroll
        for (int p = 0; p < NOCP; p++) {
            float lo, hi;
            UNPK2(lo, hi, acc[p]);
            outb[(2 * p) * N_PIX]     = lo;
            outb[(2 * p + 1) * N_PIX] = hi;
        }
    } else {
        // fused stats: mean / unbiased std over 16 channels, write xc + inv-std
        float v[16];
        float s = 0.f;
        #pragma unroll
        for (int p = 0; p < NOCP; p++) {
            UNPK2(v[2 * p], v[2 * p + 1], acc[p]);
            s += v[2 * p] + v[2 * p + 1];
        }
        float mean = s * (1.f / 16.f);
        float var = 0.f;
        float* xcb = g_xc + b * CH * N_PIX + pix;
        #pragma unroll
        for (int c = 0; c < 16; c++) {
            float d = v[c] - mean;
            var = fmaf(d, d, var);
            xcb[c * N_PIX] = d;
        }
        var *= (1.f / 15.f);        // ddof = 1
        g_invs[b * N_PIX + pix] = rsqrtf(var) ;
    }
}

// ---------------- coupling: out[b,i,j] = (xc_i . xc_j)/16 * s_i * s_j * mask ----------------
// Symmetric: only tj >= ti tiles computed; transpose mirrored via SMEM staging.
__global__ void __launch_bounds__(256) coupling_kernel(const float* __restrict__ mask,
                                                       float* __restrict__ out) {
    __shared__ __align__(16) float sxi[16 * 64];
    __shared__ __align__(16) float sxj[16 * 64];
    __shared__ float sii[64];
    __shared__ float sij[64];
    __shared__ float stg[64 * 65];

    int b = blockIdx.x;             // batch fastest -> mask tiles reused in L2 across batches
    int p = blockIdx.y;             // 0..2079 triangular pair index (T=64)

    int ti = (int)((129.0f - sqrtf(129.0f * 129.0f - 8.0f * (float)p)) * 0.5f);
    while (((ti + 1) * 64 - ((ti + 1) * ti) / 2) <= p) ti++;
    while ((ti * 64 - (ti * (ti - 1)) / 2) > p) ti--;
    int tj = ti + (p - (ti * 64 - (ti * (ti - 1)) / 2));
    bool diag = (ti == tj);

    int tid = threadIdx.x;
    const float* xcb = g_xc + b * CH * N_PIX;
    for (int idx = tid; idx < 1024; idx += 256) {
        int c = idx >> 6, col = idx & 63;
        sxi[idx] = xcb[c * N_PIX + ti * 64 + col];
        sxj[idx] = xcb[c * N_PIX + tj * 64 + col];
    }
    if (tid < 64)       sii[tid]      = g_invs[b * N_PIX + ti * 64 + tid];
    else if (tid < 128) sij[tid - 64] = g_invs[b * N_PIX + tj * 64 + tid - 64];
    __syncthreads();

    int txj = tid & 15, tyi = tid >> 4;
    int jl = txj * 4, il = tyi * 4;

    unsigned long long a0[4], a1[4];
    #pragma unroll
    for (int ii = 0; ii < 4; ii++) { a0[ii] = 0ULL; a1[ii] = 0ULL; }

    #pragma unroll
    for (int c = 0; c < 16; c++) {
        unsigned long long pb0 = *reinterpret_cast<const unsigned long long*>(&sxj[c * 64 + jl]);
        unsigned long long pb1 = *reinterpret_cast<const unsigned long long*>(&sxj[c * 64 + jl + 2]);
        #pragma unroll
        for (int ii = 0; ii < 4; ii++) {
            float av = sxi[c * 64 + il + ii];
            unsigned long long pa;
            DUP2(pa, av);
            FMA2(a0[ii], pa, pb0);
            FMA2(a1[ii], pa, pb1);
        }
    }

    float sj0 = sij[jl], sj1 = sij[jl + 1], sj2 = sij[jl + 2], sj3 = sij[jl + 3];
    size_t obase = (size_t)b * N_PIX * N_PIX;

    #pragma unroll
    for (int ii = 0; ii < 4; ii++) {
        float v0, v1, v2, v3;
        UNPK2(v0, v1, a0[ii]);
        UNPK2(v2, v3, a1[ii]);
        float si = sii[il + ii] * 0.0625f;     // fold /16
        v0 *= si * sj0; v1 *= si * sj1; v2 *= si * sj2; v3 *= si * sj3;

        if (!diag) {   // transposed staging for mirror write (mask not applied yet)
            stg[(jl + 0) * 65 + il + ii] = v0;
            stg[(jl + 1) * 65 + il + ii] = v1;
            stg[(jl + 2) * 65 + il + ii] = v2;
            stg[(jl + 3) * 65 + il + ii] = v3;
        }

        int ig = ti * 64 + il + ii;
        int jg = tj * 64 + jl;
        float4 m = *reinterpret_cast<const float4*>(mask + (size_t)ig * N_PIX + jg);
        float4 o = make_float4(v0 * m.x, v1 * m.y, v2 * m.z, v3 * m.w);
        *reinterpret_cast<float4*>(out + obase + (size_t)ig * N_PIX + jg) = o;
    }

    if (!diag) {   // block-uniform branch -> syncthreads is safe
        __syncthreads();
        #pragma unroll
        for (int rr = 0; rr < 4; rr++) {
            int r  = il + rr;                // local j row
            int jg = tj * 64 + r;
            int c0 = jl;                     // local i col
            float s0 = stg[r * 65 + c0 + 0];
            float s1 = stg[r * 65 + c0 + 1];
            float s2 = stg[r * 65 + c0 + 2];
            float s3 = stg[r * 65 + c0 + 3];
            float4 m = *reinterpret_cast<const float4*>(mask + (size_t)jg * N_PIX + ti * 64 + c0);
            float4 o = make_float4(s0 * m.x, s1 * m.y, s2 * m.z, s3 * m.w);
            *reinterpret_cast<float4*>(out + obase + (size_t)jg * N_PIX + ti * 64 + c0) = o;
        }
    }
}

// ---------------- launch ----------------
extern "C" void kernel_launch(void* const* d_in, const int* in_sizes, int n_in,
                              void* d_out, int out_size) {
    const float* x    = (const float*)d_in[0];
    const float* w0   = (const float*)d_in[1];
    const float* b0   = (const float*)d_in[2];
    const float* w1   = (const float*)d_in[3];
    const float* b1   = (const float*)d_in[4];
    const float* w2   = (const float*)d_in[5];
    const float* b2   = (const float*)d_in[6];
    const float* mask = (const float*)d_in[7];
    float* out = (float*)d_out;

    prep_kernel<<<26, 256>>>(w1, b1, w2, b2);                          // pack weight pairs
    conv0_kernel<<<(B * CH * N_PIX) / 256, 256>>>(x, w0, b0);          // x -> g_buf0
    conv16p_kernel<4, false><<<dim3(32, 2, B), 128>>>();               // g_buf0 -> g_buf1
    conv16p_kernel<8, true><<<dim3(32, B), 128>>>();                   // g_buf1 -> g_xc, g_invs
    coupling_kernel<<<dim3(B, 2080), 256>>>(mask, out);                // -> d_out
}